// round 1
// baseline (speedup 1.0000x reference)
#include <cuda_runtime.h>

#define SEQ_LEN  512
#define PRED_LEN 192
#define ENC_IN   512
#define BATCH    128

// One CTA per batch. 512 threads: thread n owns channel n for the reduction,
// then all threads cooperatively write the 192x512 output tile as float4.
__global__ __launch_bounds__(512, 1)
void trend_kernel(const float* __restrict__ x_enc, float* __restrict__ out) {
    const int b = blockIdx.x;
    const int n = threadIdx.x;

    // ---- Reduction over L: Sy = sum x, Sty = sum (l-512)*x ----
    const float* p = x_enc + (size_t)b * SEQ_LEN * ENC_IN + n;
    float sy = 0.0f, sty = 0.0f;
    #pragma unroll 8
    for (int l = 0; l < SEQ_LEN; ++l) {
        float v = p[(size_t)l * ENC_IN];
        sy += v;
        sty = fmaf((float)(l - SEQ_LEN), v, sty);
    }

    // Normal-equation constants for t = -512..-1 (all exact in fp32,
    // matching the fp32 reference):
    const float S0  = 512.0f;
    const float S1  = -131328.0f;       // sum t
    const float S2  = 44870400.0f;      // sum t^2
    const float det = 5726601216.0f;    // S0*S2 - S1*S1

    float intercept = (S2 * sy - S1 * sty) / det;
    float slope     = (S0 * sty - S1 * sy) / det;

    __shared__ float sI[ENC_IN];
    __shared__ float sS[ENC_IN];
    sI[n] = intercept;
    sS[n] = slope;
    __syncthreads();

    // ---- Write phase: dec_out, t_out (identical), s_out (zeros) ----
    const size_t SEC = (size_t)BATCH * PRED_LEN * ENC_IN;   // floats per output tensor
    const size_t tile_off4 = (size_t)b * PRED_LEN * ENC_IN / 4;

    float4* __restrict__ dec = reinterpret_cast<float4*>(out) + tile_off4;
    float4* __restrict__ tou = reinterpret_cast<float4*>(out + SEC) + tile_off4;
    float4* __restrict__ sou = reinterpret_cast<float4*>(out + 2 * SEC) + tile_off4;

    const float4* sI4 = reinterpret_cast<const float4*>(sI);
    const float4* sS4 = reinterpret_cast<const float4*>(sS);
    const float4 zero = make_float4(0.f, 0.f, 0.f, 0.f);

    const int total4 = PRED_LEN * ENC_IN / 4;   // 24576
    #pragma unroll 4
    for (int idx = threadIdx.x; idx < total4; idx += 512) {
        int row = idx >> 7;          // / (ENC_IN/4)
        int c4  = idx & 127;
        float tn = (float)(SEQ_LEN - PRED_LEN + row);   // 320..511
        float4 I = sI4[c4];
        float4 S = sS4[c4];
        float4 v;
        v.x = fmaf(S.x, tn, I.x);
        v.y = fmaf(S.y, tn, I.y);
        v.z = fmaf(S.z, tn, I.z);
        v.w = fmaf(S.w, tn, I.w);
        dec[idx] = v;
        tou[idx] = v;
        sou[idx] = zero;
    }
}

extern "C" void kernel_launch(void* const* d_in, const int* in_sizes, int n_in,
                              void* d_out, int out_size) {
    const float* x_enc = (const float*)d_in[0];
    float* out = (float*)d_out;
    trend_kernel<<<BATCH, 512>>>(x_enc, out);
}

// round 2
// speedup vs baseline: 1.2979x; 1.2979x over previous
#include <cuda_runtime.h>

#define SEQ_LEN  512
#define PRED_LEN 192
#define ENC_IN   512
#define BATCH    128
#define LSPLIT   4
#define ROWS_PER_SPLIT (SEQ_LEN / LSPLIT)      // 128
#define WSPLIT   4
#define ROWS_PER_W (PRED_LEN / WSPLIT)         // 48

// Scratch for partial sums: [LSPLIT][BATCH][ENC_IN]
__device__ float g_psy[LSPLIT][BATCH][ENC_IN];
__device__ float g_psty[LSPLIT][BATCH][ENC_IN];

// ---------------- Kernel A: partial reduction over L ----------------
// grid = (BATCH, LSPLIT), block = 512. Thread n = channel n.
__global__ __launch_bounds__(512)
void reduce_kernel(const float* __restrict__ x_enc) {
    const int b = blockIdx.x;
    const int s = blockIdx.y;
    const int n = threadIdx.x;

    const int l0 = s * ROWS_PER_SPLIT;
    const float* p = x_enc + ((size_t)b * SEQ_LEN + l0) * ENC_IN + n;

    float sy = 0.0f, sty = 0.0f;
    #pragma unroll 8
    for (int i = 0; i < ROWS_PER_SPLIT; ++i) {
        float v = p[(size_t)i * ENC_IN];
        sy += v;
        sty = fmaf((float)(l0 + i - SEQ_LEN), v, sty);
    }
    g_psy[s][b][n]  = sy;
    g_psty[s][b][n] = sty;
}

// ---------------- Kernel B: combine + write outputs ----------------
// grid = (BATCH, WSPLIT), block = 512.
__global__ __launch_bounds__(512)
void write_kernel(float* __restrict__ out) {
    const int b = blockIdx.x;
    const int w = blockIdx.y;
    const int n = threadIdx.x;

    // Combine partials for channel n
    float sy  = g_psy[0][b][n]  + g_psy[1][b][n]  + g_psy[2][b][n]  + g_psy[3][b][n];
    float sty = g_psty[0][b][n] + g_psty[1][b][n] + g_psty[2][b][n] + g_psty[3][b][n];

    // Normal-equation constants for t = -512..-1 (exact in fp32):
    const float S0  = 512.0f;
    const float S1  = -131328.0f;
    const float S2  = 44870400.0f;
    const float det = 5726601216.0f;

    float intercept = (S2 * sy - S1 * sty) / det;
    float slope     = (S0 * sty - S1 * sy) / det;

    __shared__ float sI[ENC_IN];
    __shared__ float sS[ENC_IN];
    sI[n] = intercept;
    sS[n] = slope;
    __syncthreads();

    const size_t SEC = (size_t)BATCH * PRED_LEN * ENC_IN;  // floats per tensor
    const int row0 = w * ROWS_PER_W;                       // 0,48,96,144
    const size_t tile_off4 = ((size_t)b * PRED_LEN + row0) * ENC_IN / 4;

    float4* __restrict__ dec = reinterpret_cast<float4*>(out) + tile_off4;
    float4* __restrict__ tou = reinterpret_cast<float4*>(out + SEC) + tile_off4;
    float4* __restrict__ sou = reinterpret_cast<float4*>(out + 2 * SEC) + tile_off4;

    const float4* sI4 = reinterpret_cast<const float4*>(sI);
    const float4* sS4 = reinterpret_cast<const float4*>(sS);
    const float4 zero = make_float4(0.f, 0.f, 0.f, 0.f);

    const int total4 = ROWS_PER_W * ENC_IN / 4;   // 6144
    #pragma unroll 4
    for (int idx = n; idx < total4; idx += 512) {
        int row = idx >> 7;          // / (ENC_IN/4)
        int c4  = idx & 127;
        // global prediction time index: t_new = 320 + row0 + row
        float tn = (float)(SEQ_LEN - PRED_LEN + row0 + row);
        float4 I = sI4[c4];
        float4 S = sS4[c4];
        float4 v;
        v.x = fmaf(S.x, tn, I.x);
        v.y = fmaf(S.y, tn, I.y);
        v.z = fmaf(S.z, tn, I.z);
        v.w = fmaf(S.w, tn, I.w);
        dec[idx] = v;
        tou[idx] = v;
        sou[idx] = zero;
    }
}

extern "C" void kernel_launch(void* const* d_in, const int* in_sizes, int n_in,
                              void* d_out, int out_size) {
    const float* x_enc = (const float*)d_in[0];
    float* out = (float*)d_out;
    reduce_kernel<<<dim3(BATCH, LSPLIT), 512>>>(x_enc);
    write_kernel<<<dim3(BATCH, WSPLIT), 512>>>(out);
}

// round 3
// speedup vs baseline: 1.3906x; 1.0714x over previous
#include <cuda_runtime.h>

#define SEQ_LEN  512
#define PRED_LEN 192
#define ENC_IN   512
#define BATCH    128
#define CSPLIT   4
#define CH_PER_CTA (ENC_IN / CSPLIT)   // 128 channels -> 32 float4 lanes
#define NT       256

// Fused: grid (BATCH, CSPLIT), block 256.
// Each CTA handles one (batch, 128-channel group): reduce over L, solve, write.
__global__ __launch_bounds__(NT)
void fused_trend_kernel(const float* __restrict__ x_enc, float* __restrict__ out) {
    const int b    = blockIdx.x;
    const int cg   = blockIdx.y;
    const int t    = threadIdx.x;
    const int lane = t & 31;       // float4 column within channel group (0..31)
    const int rsub = t >> 5;       // row subgroup (0..7)
    const int c0   = cg * CH_PER_CTA;

    const size_t SEC = (size_t)BATCH * PRED_LEN * ENC_IN;   // floats per tensor
    const size_t tile_f = (size_t)b * PRED_LEN * ENC_IN + c0;
    const float4 zero = make_float4(0.f, 0.f, 0.f, 0.f);

    // ---- Early: s_out zeros (no dependency) — overlaps with the read phase ----
    {
        float4* __restrict__ sou = reinterpret_cast<float4*>(out + 2 * SEC + tile_f);
        #pragma unroll 4
        for (int idx = t; idx < PRED_LEN * 32; idx += NT) {
            int row = idx >> 5;
            int c4  = idx & 31;
            sou[(size_t)row * (ENC_IN / 4) + c4] = zero;
        }
    }

    // ---- Reduction over L (float4 per thread, 8 row-subgroups) ----
    const float4* __restrict__ px =
        reinterpret_cast<const float4*>(x_enc + (size_t)b * SEQ_LEN * ENC_IN + c0);

    float4 sy  = zero;
    float4 sty = zero;
    #pragma unroll 8
    for (int i = 0; i < SEQ_LEN / 8; ++i) {
        int r = i * 8 + rsub;
        float4 v = px[(size_t)r * (ENC_IN / 4) + lane];
        float tc = (float)(r - SEQ_LEN);          // t in [-512, -1]
        sy.x += v.x;  sy.y += v.y;  sy.z += v.z;  sy.w += v.w;
        sty.x = fmaf(tc, v.x, sty.x);
        sty.y = fmaf(tc, v.y, sty.y);
        sty.z = fmaf(tc, v.z, sty.z);
        sty.w = fmaf(tc, v.w, sty.w);
    }

    __shared__ float4 red_sy[8][32];
    __shared__ float4 red_sty[8][32];
    __shared__ float4 sI4[32];
    __shared__ float4 sS4[32];

    red_sy[rsub][lane]  = sy;
    red_sty[rsub][lane] = sty;
    __syncthreads();

    if (t < 32) {
        float4 a = red_sy[0][t];
        float4 c = red_sty[0][t];
        #pragma unroll
        for (int k = 1; k < 8; ++k) {
            float4 u = red_sy[k][t];
            float4 w = red_sty[k][t];
            a.x += u.x; a.y += u.y; a.z += u.z; a.w += u.w;
            c.x += w.x; c.y += w.y; c.z += w.z; c.w += w.w;
        }
        // Normal-equation constants for t = -512..-1 (exact in fp32):
        const float S0  = 512.0f;
        const float S1  = -131328.0f;
        const float S2  = 44870400.0f;
        const float det = 5726601216.0f;

        float4 I, S;
        I.x = (S2 * a.x - S1 * c.x) / det;  S.x = (S0 * c.x - S1 * a.x) / det;
        I.y = (S2 * a.y - S1 * c.y) / det;  S.y = (S0 * c.y - S1 * a.y) / det;
        I.z = (S2 * a.z - S1 * c.z) / det;  S.z = (S0 * c.z - S1 * a.z) / det;
        I.w = (S2 * a.w - S1 * c.w) / det;  S.w = (S0 * c.w - S1 * a.w) / det;
        sI4[t] = I;
        sS4[t] = S;
    }
    __syncthreads();

    // ---- Write dec_out and t_out (identical values) ----
    float4* __restrict__ dec = reinterpret_cast<float4*>(out + tile_f);
    float4* __restrict__ tou = reinterpret_cast<float4*>(out + SEC + tile_f);

    #pragma unroll 4
    for (int idx = t; idx < PRED_LEN * 32; idx += NT) {
        int row = idx >> 5;
        int c4  = idx & 31;
        float tn = (float)(SEQ_LEN - PRED_LEN + row);   // 320..511
        float4 I = sI4[c4];
        float4 S = sS4[c4];
        float4 v;
        v.x = fmaf(S.x, tn, I.x);
        v.y = fmaf(S.y, tn, I.y);
        v.z = fmaf(S.z, tn, I.z);
        v.w = fmaf(S.w, tn, I.w);
        size_t off = (size_t)row * (ENC_IN / 4) + c4;
        dec[off] = v;
        tou[off] = v;
    }
}

extern "C" void kernel_launch(void* const* d_in, const int* in_sizes, int n_in,
                              void* d_out, int out_size) {
    const float* x_enc = (const float*)d_in[0];
    float* out = (float*)d_out;
    fused_trend_kernel<<<dim3(BATCH, CSPLIT), NT>>>(x_enc, out);
}